// round 1
// baseline (speedup 1.0000x reference)
#include <cuda_runtime.h>
#include <stdint.h>

#define NB 8
#define NC 80
#define NA 3
#define NHW 5776
#define NN (NA * NHW)      /* 17328 */
#define TOPK 200
#define NBINS 4096
#define STASH_BIN 3932     /* bin of ~0.98: mantissa>>11 */
#define STASH_CAP 1024
#define CAND_CAP 1024
#define SORT_M 1024
#define NW 7               /* ceil(200/32) keep-mask words */

// 44.3 MB scratch for transposed scores [B][C][N] (static device array: allowed)
__device__ float g_scoresT[(size_t)NB * NC * NN];

// ---------------------------------------------------------------------------
// Kernel 1: transpose scores (B, N, C) -> (B, C, N), tiled via shared memory.
// N = 17328 = 48 * 361.
// ---------------------------------------------------------------------------
__global__ __launch_bounds__(256) void transpose_k(const float* __restrict__ scores) {
    __shared__ float tile[48 * 81];   // pad 80->81 to kill bank conflicts
    const int b  = blockIdx.y;
    const int n0 = blockIdx.x * 48;
    const float* src = scores + ((size_t)b * NN + n0) * NC;

    // contiguous 48*80 floats -> smem
    for (int i = threadIdx.x; i < 48 * NC; i += 256) {
        int r = i / NC, c = i % NC;
        tile[r * 81 + c] = src[i];
    }
    __syncthreads();

    // write transposed: per class c, 48 contiguous n values (192B segments)
    for (int j = threadIdx.x; j < NC * 48; j += 256) {
        int c = j / 48, r = j % 48;
        g_scoresT[((size_t)b * NC + c) * NN + n0 + r] = tile[r * 81 + c];
    }
}

// ---------------------------------------------------------------------------
// Kernel 2: one CTA per (b, c). Exact top-200 (value desc, tie -> lower index)
// via histogram radix-cut + stash, bitonic sort of candidates, greedy NMS via
// suppression bitmask matrix, masked output write.
// ---------------------------------------------------------------------------
__device__ __forceinline__ uint32_t score_bin(uint32_t bits) {
    // bits correspond to a float v with v > 0.5f (so bits > 0x3F000000)
    return (bits >= 0x3F800000u) ? (NBINS - 1) : ((bits - 0x3F000000u) >> 11);
}

__global__ __launch_bounds__(256) void nms_k(const float* __restrict__ boxes,
                                             float* __restrict__ out) {
    const int bc  = blockIdx.x;          // = b*NC + c
    const int b   = bc / NC;
    const int c   = bc % NC;
    const int tid = threadIdx.x;
    const float* base = g_scoresT + (size_t)bc * NN;

    __shared__ uint32_t hist[NBINS];
    __shared__ unsigned long long stash[STASH_CAP];
    __shared__ unsigned long long cand[CAND_CAP];
    __shared__ uint32_t part[256];
    __shared__ uint32_t stashCnt, candCnt;
    __shared__ int cutBin;
    __shared__ float sx1[TOPK], sy1[TOPK], sx2[TOPK], sy2[TOPK], sar[TOPK], ssc[TOPK];
    __shared__ uint32_t smat[TOPK * NW];
    __shared__ uint32_t skeepw[NW];

    for (int i = tid; i < NBINS; i += 256) hist[i] = 0u;
    if (tid == 0) { stashCnt = 0u; candCnt = 0u; }
    __syncthreads();

    // ---- Pass 1: histogram + stash of high scores (coalesced read) ----
    for (int i = tid; i < NN; i += 256) {
        float v = base[i];
        if (v > 0.5f) {
            uint32_t bits = __float_as_uint(v);
            uint32_t bin  = score_bin(bits);
            atomicAdd(&hist[bin], 1u);
            if (bin >= STASH_BIN) {
                uint32_t p = atomicAdd(&stashCnt, 1u);
                if (p < STASH_CAP)
                    stash[p] = ((unsigned long long)bits << 32) | (uint32_t)(~(uint32_t)i);
            }
        }
    }
    __syncthreads();

    // ---- Find exact cutoff bin h* = max h with suffix_count(h) >= TOPK ----
    uint32_t ps = 0;
    #pragma unroll
    for (int k = 0; k < 16; k++) ps += hist[tid * 16 + k];
    part[tid] = ps;
    __syncthreads();
    if (tid == 0) {
        uint32_t suf = 0; int g = -1; uint32_t sufAfterG = 0;
        for (int t = 255; t >= 0; t--) {
            uint32_t ns = suf + part[t];
            if (ns >= TOPK) { g = t; sufAfterG = suf; break; }
            suf = ns;
        }
        int hstar = 0;
        if (g >= 0) {
            uint32_t run = sufAfterG;
            for (int bn = g * 16 + 15; bn >= g * 16; bn--) {
                run += hist[bn];
                if (run >= TOPK) { hstar = bn; break; }
            }
        }
        cutBin = hstar;
    }
    __syncthreads();

    const int hstar = cutBin;
    const bool stashOK = (hstar >= STASH_BIN) && (stashCnt <= STASH_CAP);

    // ---- Collect candidates (bin >= h*) ----
    if (stashOK) {
        int sc = (int)stashCnt;
        for (int i = tid; i < sc; i += 256) {
            unsigned long long key = stash[i];
            uint32_t bits = (uint32_t)(key >> 32);
            if (score_bin(bits) >= (uint32_t)hstar) {
                uint32_t p = atomicAdd(&candCnt, 1u);
                if (p < CAND_CAP) cand[p] = key;
            }
        }
    } else {
        // rare fallback: rescan (L2-resident)
        for (int i = tid; i < NN; i += 256) {
            float v = base[i];
            if (v > 0.5f) {
                uint32_t bits = __float_as_uint(v);
                if (score_bin(bits) >= (uint32_t)hstar) {
                    uint32_t p = atomicAdd(&candCnt, 1u);
                    if (p < CAND_CAP)
                        cand[p] = ((unsigned long long)bits << 32) | (uint32_t)(~(uint32_t)i);
                }
            }
        }
    }
    __syncthreads();

    const int cc = (candCnt < (uint32_t)CAND_CAP) ? (int)candCnt : CAND_CAP;
    for (int i = tid; i < SORT_M; i += 256)
        if (i >= cc) cand[i] = 0ULL;   // pad: sorts last (descending)
    __syncthreads();

    // ---- Bitonic sort, descending, M=1024 keys ----
    for (int k = 2; k <= SORT_M; k <<= 1) {
        for (int j = k >> 1; j > 0; j >>= 1) {
            for (int i = tid; i < SORT_M; i += 256) {
                int ixj = i ^ j;
                if (ixj > i) {
                    unsigned long long a = cand[i], bb = cand[ixj];
                    bool desc = ((i & k) == 0);
                    if (desc ? (a < bb) : (a > bb)) { cand[i] = bb; cand[ixj] = a; }
                }
            }
            __syncthreads();
        }
    }

    const int nTop = (cc < TOPK) ? cc : TOPK;

    // ---- Gather boxes of winners ----
    if (tid < TOPK) {
        if (tid < nTop) {
            unsigned long long key = cand[tid];
            uint32_t idx = ~(uint32_t)(key & 0xFFFFFFFFull);
            float sc = __uint_as_float((uint32_t)(key >> 32));
            float4 bx = reinterpret_cast<const float4*>(boxes)[(size_t)b * NN + idx];
            sx1[tid] = bx.x; sy1[tid] = bx.y; sx2[tid] = bx.z; sy2[tid] = bx.w;
            sar[tid] = (bx.z - bx.x) * (bx.w - bx.y);
            ssc[tid] = sc;
        } else {
            sx1[tid] = sy1[tid] = sx2[tid] = sy2[tid] = 0.f;
            sar[tid] = 0.f; ssc[tid] = 0.f;
        }
    }
    __syncthreads();

    // ---- Suppression matrix: bit (i, j) set iff j > i && iou > 0.5 ----
    for (int idx = tid; idx < TOPK * NW; idx += 256) {
        int i = idx / NW, w = idx % NW;
        uint32_t m = 0u;
        if (i < nTop) {
            float x1 = sx1[i], y1 = sy1[i], x2 = sx2[i], y2 = sy2[i], ai = sar[i];
            int j0 = w * 32;
            int jend = j0 + 32; if (jend > nTop) jend = nTop;
            int jbeg = (i + 1 > j0) ? (i + 1) : j0;
            for (int j = jbeg; j < jend; j++) {
                float xx1 = fmaxf(x1, sx1[j]), yy1 = fmaxf(y1, sy1[j]);
                float xx2 = fminf(x2, sx2[j]), yy2 = fminf(y2, sy2[j]);
                float inter = fmaxf(0.f, xx2 - xx1) * fmaxf(0.f, yy2 - yy1);
                float iou = inter / (ai + sar[j] - inter);
                if (iou > 0.5f) m |= (1u << (j - j0));
            }
        }
        smat[i * NW + w] = m;
    }
    __syncthreads();

    // ---- Greedy scan (matches reference jax.lax.scan exactly) ----
    if (tid == 0) {
        uint32_t rm[NW];
        #pragma unroll
        for (int w = 0; w < NW; w++) rm[w] = 0u;
        for (int i = 0; i < nTop; i++) {
            if (!((rm[i >> 5] >> (i & 31)) & 1u)) {
                #pragma unroll
                for (int w = 0; w < NW; w++) rm[w] |= smat[i * NW + w];
            }
        }
        #pragma unroll
        for (int w = 0; w < NW; w++) skeepw[w] = ~rm[w];
    }
    __syncthreads();

    // ---- Output: (B, C, K, 6) = [x1,y1,x2,y2,score,cls], zero if !keep ----
    if (tid < TOPK) {
        bool kp = (tid < nTop) && ((skeepw[tid >> 5] >> (tid & 31)) & 1u);
        size_t o = ((size_t)bc * TOPK + tid) * 6;
        out[o + 0] = kp ? sx1[tid] : 0.f;
        out[o + 1] = kp ? sy1[tid] : 0.f;
        out[o + 2] = kp ? sx2[tid] : 0.f;
        out[o + 3] = kp ? sy2[tid] : 0.f;
        out[o + 4] = kp ? ssc[tid] : 0.f;
        out[o + 5] = kp ? (float)c : 0.f;
    }
}

// ---------------------------------------------------------------------------
extern "C" void kernel_launch(void* const* d_in, const int* in_sizes, int n_in,
                              void* d_out, int out_size) {
    const float* boxes  = (const float*)d_in[0];   // (8, 3, 5776, 4)
    const float* scores = (const float*)d_in[1];   // (8, 3, 5776, 80)
    float* out = (float*)d_out;                    // (8, 80, 200, 6)

    dim3 g1(NN / 48, NB);
    transpose_k<<<g1, 256>>>(scores);
    nms_k<<<NB * NC, 256>>>(boxes, out);
}

// round 2
// speedup vs baseline: 1.6745x; 1.6745x over previous
#include <cuda_runtime.h>
#include <stdint.h>

#define NB 8
#define NC 80
#define NA 3
#define NHW 5776
#define NN (NA * NHW)      /* 17328 */
#define TOPK 200
#define NBINS 4096
#define STASH_BIN 3932     /* bin of ~0.98 */
#define STASH_CAP 512
#define CAND_CAP 512
#define NW 7               /* ceil(200/32) keep-mask words */

// 44.3 MB scratch for transposed scores [B][C][N]
__device__ float g_scoresT[(size_t)NB * NC * NN];

// ---------------------------------------------------------------------------
// Kernel 1: transpose scores (B, N, C) -> (B, C, N), float4 gmem I/O.
// ---------------------------------------------------------------------------
__global__ __launch_bounds__(256) void transpose_k(const float* __restrict__ scores) {
    __shared__ float tile[48 * 81];   // pad 80->81
    const int b  = blockIdx.y;
    const int n0 = blockIdx.x * 48;
    const float4* src4 = reinterpret_cast<const float4*>(
        scores + ((size_t)b * NN + n0) * NC);

    // 48 rows * 20 float4 = 960 coalesced float4 loads
    for (int f = threadIdx.x; f < 48 * 20; f += 256) {
        float4 v = src4[f];
        int r = f / 20, c4 = f % 20;
        float* p = &tile[r * 81 + c4 * 4];
        p[0] = v.x; p[1] = v.y; p[2] = v.z; p[3] = v.w;
    }
    __syncthreads();

    // per class c: 12 float4 (48 n values), coalesced-segment stores
    for (int f = threadIdx.x; f < NC * 12; f += 256) {
        int c = f / 12, rq = f % 12;
        float4 v = make_float4(tile[(rq * 4 + 0) * 81 + c],
                               tile[(rq * 4 + 1) * 81 + c],
                               tile[(rq * 4 + 2) * 81 + c],
                               tile[(rq * 4 + 3) * 81 + c]);
        *reinterpret_cast<float4*>(
            &g_scoresT[((size_t)b * NC + c) * NN + n0 + rq * 4]) = v;
    }
}

// ---------------------------------------------------------------------------
// Kernel 2: one CTA per (b, c).
// ---------------------------------------------------------------------------
__device__ __forceinline__ uint32_t score_bin(uint32_t bits) {
    return (bits >= 0x3F800000u) ? (NBINS - 1) : ((bits - 0x3F000000u) >> 11);
}

__global__ __launch_bounds__(256) void nms_k(const float* __restrict__ boxes,
                                             float* __restrict__ out) {
    const int bc  = blockIdx.x;
    const int b   = bc / NC;
    const int c   = bc % NC;
    const int tid = threadIdx.x;
    const float* base = g_scoresT + (size_t)bc * NN;

    __shared__ uint32_t hist[NBINS];
    __shared__ unsigned long long stash[STASH_CAP];
    __shared__ unsigned long long cand[CAND_CAP];
    __shared__ uint32_t part[256];
    __shared__ uint32_t stashCnt, candCnt;
    __shared__ int cutBin;
    __shared__ float4 sbox[TOPK];
    __shared__ float sar[TOPK], ssc[TOPK];
    __shared__ uint32_t smat[TOPK * NW];
    __shared__ uint32_t skeepw[NW];

    for (int i = tid; i < NBINS; i += 256) hist[i] = 0u;
    if (tid == 0) { stashCnt = 0u; candCnt = 0u; }
    __syncthreads();

    // ---- Pass 1: float4 histogram + stash ----
    const float4* base4 = reinterpret_cast<const float4*>(base);
    for (int k = tid; k < NN / 4; k += 256) {
        float4 v4 = base4[k];
        float vv[4] = {v4.x, v4.y, v4.z, v4.w};
        #pragma unroll
        for (int u = 0; u < 4; u++) {
            float v = vv[u];
            if (v > 0.5f) {
                uint32_t bits = __float_as_uint(v);
                uint32_t bin  = score_bin(bits);
                atomicAdd(&hist[bin], 1u);
                if (bin >= STASH_BIN) {
                    uint32_t p = atomicAdd(&stashCnt, 1u);
                    if (p < STASH_CAP) {
                        uint32_t i = (uint32_t)(4 * k + u);
                        stash[p] = ((unsigned long long)bits << 32) | (~i);
                    }
                }
            }
        }
    }
    __syncthreads();

    // ---- Exact cutoff bin ----
    uint32_t ps = 0;
    #pragma unroll
    for (int k = 0; k < 16; k++) ps += hist[tid * 16 + k];
    part[tid] = ps;
    __syncthreads();
    if (tid == 0) {
        uint32_t suf = 0; int g = -1; uint32_t sufAfterG = 0;
        for (int t = 255; t >= 0; t--) {
            uint32_t ns = suf + part[t];
            if (ns >= TOPK) { g = t; sufAfterG = suf; break; }
            suf = ns;
        }
        int hstar = 0;
        if (g >= 0) {
            uint32_t run = sufAfterG;
            for (int bn = g * 16 + 15; bn >= g * 16; bn--) {
                run += hist[bn];
                if (run >= TOPK) { hstar = bn; break; }
            }
        }
        cutBin = hstar;
    }
    __syncthreads();

    const int hstar = cutBin;
    const bool stashOK = (hstar >= STASH_BIN) && (stashCnt <= STASH_CAP);

    // ---- Collect candidates ----
    if (stashOK) {
        int sc = (int)stashCnt;
        for (int i = tid; i < sc; i += 256) {
            unsigned long long key = stash[i];
            uint32_t bits = (uint32_t)(key >> 32);
            if (score_bin(bits) >= (uint32_t)hstar) {
                uint32_t p = atomicAdd(&candCnt, 1u);
                if (p < CAND_CAP) cand[p] = key;
            }
        }
    } else {
        for (int i = tid; i < NN; i += 256) {
            float v = base[i];
            if (v > 0.5f) {
                uint32_t bits = __float_as_uint(v);
                if (score_bin(bits) >= (uint32_t)hstar) {
                    uint32_t p = atomicAdd(&candCnt, 1u);
                    if (p < CAND_CAP)
                        cand[p] = ((unsigned long long)bits << 32) | (~(uint32_t)i);
                }
            }
        }
    }
    __syncthreads();

    const int cc = (candCnt < (uint32_t)CAND_CAP) ? (int)candCnt : CAND_CAP;
    const int M  = (cc <= 256) ? 256 : 512;
    for (int i = tid; i < M; i += 256)
        if (i >= cc) cand[i] = 0ULL;
    __syncthreads();

    // ---- Bitonic sort, descending, runtime M ----
    for (int k = 2; k <= M; k <<= 1) {
        for (int j = k >> 1; j > 0; j >>= 1) {
            for (int i = tid; i < M; i += 256) {
                int ixj = i ^ j;
                if (ixj > i) {
                    unsigned long long a = cand[i], bb = cand[ixj];
                    bool desc = ((i & k) == 0);
                    if (desc ? (a < bb) : (a > bb)) { cand[i] = bb; cand[ixj] = a; }
                }
            }
            __syncthreads();
        }
    }

    const int nTop = (cc < TOPK) ? cc : TOPK;

    // ---- Gather winner boxes ----
    if (tid < TOPK) {
        if (tid < nTop) {
            unsigned long long key = cand[tid];
            uint32_t idx = ~(uint32_t)(key & 0xFFFFFFFFull);
            float sc = __uint_as_float((uint32_t)(key >> 32));
            float4 bx = reinterpret_cast<const float4*>(boxes)[(size_t)b * NN + idx];
            sbox[tid] = bx;
            sar[tid]  = (bx.z - bx.x) * (bx.w - bx.y);
            ssc[tid]  = sc;
        } else {
            sbox[tid] = make_float4(0.f, 0.f, 0.f, 0.f);
            sar[tid]  = 0.f; ssc[tid] = 0.f;
        }
    }
    __syncthreads();

    // ---- Suppression matrix (division-free fast path) ----
    for (int idx = tid; idx < TOPK * NW; idx += 256) {
        int i = idx / NW, w = idx % NW;
        uint32_t m = 0u;
        if (i < nTop) {
            float4 bi = sbox[i];
            float  ai = sar[i];
            int j0 = w * 32;
            int jend = j0 + 32; if (jend > nTop) jend = nTop;
            int jbeg = (i + 1 > j0) ? (i + 1) : j0;
            for (int j = jbeg; j < jend; j++) {
                float4 bj = sbox[j];
                float xx1 = fmaxf(bi.x, bj.x), yy1 = fmaxf(bi.y, bj.y);
                float xx2 = fminf(bi.z, bj.z), yy2 = fminf(bi.w, bj.w);
                float inter = fmaxf(0.f, xx2 - xx1) * fmaxf(0.f, yy2 - yy1);
                float denom = ai + sar[j] - inter;
                float t2 = inter + inter;
                bool sup;
                if (t2 > denom * 1.00002f)      sup = true;
                else if (t2 < denom * 0.99998f) sup = false;
                else                            sup = (inter / denom > 0.5f);
                if (sup) m |= (1u << (j - j0));
            }
        }
        smat[i * NW + w] = m;
    }
    __syncthreads();

    // ---- Greedy scan (exact reference semantics) ----
    if (tid == 0) {
        uint32_t rm[NW];
        #pragma unroll
        for (int w = 0; w < NW; w++) rm[w] = 0u;
        for (int i = 0; i < nTop; i++) {
            if (!((rm[i >> 5] >> (i & 31)) & 1u)) {
                #pragma unroll
                for (int w = 0; w < NW; w++) rm[w] |= smat[i * NW + w];
            }
        }
        #pragma unroll
        for (int w = 0; w < NW; w++) skeepw[w] = ~rm[w];
    }
    __syncthreads();

    // ---- Output ----
    if (tid < TOPK) {
        bool kp = (tid < nTop) && ((skeepw[tid >> 5] >> (tid & 31)) & 1u);
        size_t o = ((size_t)bc * TOPK + tid) * 6;
        float4 bx = sbox[tid];
        out[o + 0] = kp ? bx.x : 0.f;
        out[o + 1] = kp ? bx.y : 0.f;
        out[o + 2] = kp ? bx.z : 0.f;
        out[o + 3] = kp ? bx.w : 0.f;
        out[o + 4] = kp ? ssc[tid] : 0.f;
        out[o + 5] = kp ? (float)c : 0.f;
    }
}

// ---------------------------------------------------------------------------
extern "C" void kernel_launch(void* const* d_in, const int* in_sizes, int n_in,
                              void* d_out, int out_size) {
    const float* boxes  = (const float*)d_in[0];
    const float* scores = (const float*)d_in[1];
    float* out = (float*)d_out;

    dim3 g1(NN / 48, NB);
    transpose_k<<<g1, 256>>>(scores);
    nms_k<<<NB * NC, 256>>>(boxes, out);
}